// round 4
// baseline (speedup 1.0000x reference)
#include <cuda_runtime.h>
#include <cuda_fp16.h>
#include <cstdint>

#define M_DIM 8192
#define K_DIM 4096
#define N_DIM 11008
#define NG_DIM 32

#define TILE_M 128
#define TILE_N 128
#define NT (N_DIM / TILE_N) /* 86 */
#define MT (M_DIM / TILE_M) /* 64 */
#define NTHREADS 256

// ---------------- scratch (static device arrays: allocation-free) ----------------
__device__ __half g_xhi[(size_t)M_DIM * K_DIM];
__device__ __half g_xlo[(size_t)M_DIM * K_DIM];
__device__ float  g_S[NG_DIM * M_DIM];   // S[g*M + m] = sum of x over group g

// ---------------- smem layout: two buffers ----------------
// per buffer: A_hi 32KB | A_lo 32KB | B 32KB | scales 512B | zeros 512B
#define B_AHI 0
#define B_ALO 32768
#define B_BB  65536
#define B_SZ  98304
#define BUF_STRIDE 99328
#define SMEM_BYTES (2 * BUF_STRIDE) /* 198656 */

// ---------------- helpers ----------------
__device__ __forceinline__ uint32_t smem_u32(const void* p) {
    uint32_t a;
    asm("{ .reg .u64 t; cvta.to.shared.u64 t, %1; cvt.u32.u64 %0, t; }" : "=r"(a) : "l"(p));
    return a;
}

#define CP_ASYNC16(dst, src) \
    asm volatile("cp.async.cg.shared.global [%0], [%1], 16;" :: "r"(dst), "l"(src))
#define CP_COMMIT() asm volatile("cp.async.commit_group;" ::: "memory")
#define CP_WAIT0()  asm volatile("cp.async.wait_group 0;" ::: "memory")

#define LDSM_X4(r0, r1, r2, r3, addr) \
    asm volatile("ldmatrix.sync.aligned.m8n8.x4.shared.b16 {%0,%1,%2,%3}, [%4];" \
                 : "=r"(r0), "=r"(r1), "=r"(r2), "=r"(r3) : "r"(addr))

#define MMA16816(d, a, b0v, b1v) \
    asm volatile("mma.sync.aligned.m16n8k16.row.col.f32.f16.f16.f32 " \
                 "{%0,%1,%2,%3}, {%4,%5,%6,%7}, {%8,%9}, {%0,%1,%2,%3};" \
                 : "+f"((d)[0]), "+f"((d)[1]), "+f"((d)[2]), "+f"((d)[3]) \
                 : "r"((a)[0]), "r"((a)[1]), "r"((a)[2]), "r"((a)[3]), \
                   "r"(b0v), "r"(b1v))

// one packed int32 word -> 8 exact fp16 nibble values, K-ascending, as 4 u32
__device__ __forceinline__ void dequant8(uint32_t w, uint32_t r[4]) {
    const uint32_t MASK = 0x000F000Fu, BIAS = 0x64006400u;
    uint32_t q0 = ((w      ) & MASK) | BIAS;
    uint32_t q1 = ((w >>  4) & MASK) | BIAS;
    uint32_t q2 = ((w >>  8) & MASK) | BIAS;
    uint32_t q3 = ((w >> 12) & MASK) | BIAS;
    __half2 off1024 = *reinterpret_cast<const __half2*>(&BIAS);
    __half2 h0 = __hsub2(*reinterpret_cast<__half2*>(&q0), off1024);
    __half2 h1 = __hsub2(*reinterpret_cast<__half2*>(&q1), off1024);
    __half2 h2 = __hsub2(*reinterpret_cast<__half2*>(&q2), off1024);
    __half2 h3 = __hsub2(*reinterpret_cast<__half2*>(&q3), off1024);
    uint32_t b0 = *reinterpret_cast<uint32_t*>(&h0);
    uint32_t b1 = *reinterpret_cast<uint32_t*>(&h1);
    uint32_t b2 = *reinterpret_cast<uint32_t*>(&h2);
    uint32_t b3 = *reinterpret_cast<uint32_t*>(&h3);
    r[0] = __byte_perm(b0, b1, 0x5410);  // k0 k1
    r[1] = __byte_perm(b2, b3, 0x5410);  // k2 k3
    r[2] = __byte_perm(b0, b1, 0x7632);  // k4 k5
    r[3] = __byte_perm(b2, b3, 0x7632);  // k6 k7
}

// ---------------- prep: split x into fp16 hi/lo planes + group sums ----------------
__global__ void prep_kernel(const float* __restrict__ x) {
    int gwarp = (blockIdx.x * blockDim.x + threadIdx.x) >> 5;
    int lane  = threadIdx.x & 31;
    if (gwarp >= M_DIM * NG_DIM) return;
    int m = gwarp / NG_DIM;
    int g = gwarp % NG_DIM;
    size_t base = (size_t)m * K_DIM + (size_t)g * 128;
    const float* xr = x + base;
    float sum = 0.f;
#pragma unroll
    for (int j = 0; j < 4; j++) {
        float v = xr[lane + 32 * j];
        __half hi = __float2half_rn(v);
        __half lo = __float2half_rn(v - __half2float(hi));
        g_xhi[base + lane + 32 * j] = hi;
        g_xlo[base + lane + 32 * j] = lo;
        sum += v;
    }
#pragma unroll
    for (int o = 16; o > 0; o >>= 1) sum += __shfl_xor_sync(0xFFFFFFFFu, sum, o);
    if (lane == 0) g_S[g * M_DIM + m] = sum;
}

// ---------------- pipeline pieces ----------------
// async fill of A planes + scale/zero rows for group g into buffer at smem u32 base sbuf
__device__ __forceinline__ void fill_group_async(
    uint32_t sbuf, int g, int m0, int n0,
    const float* __restrict__ scales, const float* __restrict__ zeros, int tid) {
#pragma unroll
    for (int i = 0; i < 8; i++) {
        int idx = tid + i * NTHREADS;           // 0..2047 : 16B chunks of one plane
        int row = idx >> 4;
        int c   = idx & 15;
        uint32_t so = (uint32_t)row * 256u + (uint32_t)((c ^ (row & 7)) << 4);
        size_t goff = (size_t)(m0 + row) * K_DIM + (size_t)g * 128 + (size_t)c * 8;
        CP_ASYNC16(sbuf + B_AHI + so, (const char*)(g_xhi + goff));
        CP_ASYNC16(sbuf + B_ALO + so, (const char*)(g_xlo + goff));
    }
    if (tid < 64) {
        const float* src;
        uint32_t dst;
        if (tid < 32) {
            src = scales + (size_t)g * N_DIM + n0 + tid * 4;
            dst = sbuf + B_SZ + tid * 16;
        } else {
            src = zeros + (size_t)g * N_DIM + n0 + (tid - 32) * 4;
            dst = sbuf + B_SZ + 512 + (tid - 32) * 16;
        }
        CP_ASYNC16(dst, src);
    }
}

__device__ __forceinline__ void ldg_w(uint32_t wv[8], const int* __restrict__ Wq,
                                      int g, int n0, int wid, int lane) {
#pragma unroll
    for (int h = 0; h < 2; h++)
#pragma unroll
        for (int j = 0; j < 4; j++)
            wv[h * 4 + j] = (uint32_t)Wq[(size_t)(g * 16 + wid + h * 8) * N_DIM
                                          + n0 + lane + j * 32];
}

__device__ __forceinline__ void sts_b(char* smem, uint32_t bufoff,
                                      const uint32_t wv[8], int wid, int lane) {
#pragma unroll
    for (int h = 0; h < 2; h++)
#pragma unroll
        for (int j = 0; j < 4; j++) {
            uint32_t r[4];
            dequant8(wv[h * 4 + j], r);
            int row = lane + j * 32;          // n within tile
            int kp  = wid + h * 8;            // 16B k-chunk
            uint32_t so = (uint32_t)row * 256u + (uint32_t)((kp ^ (row & 7)) << 4);
            *(uint4*)(smem + bufoff + B_BB + so) = make_uint4(r[0], r[1], r[2], r[3]);
        }
}

// ---------------- main GEMM: 8 warps, warp tile 32m x 64n, double-buffered ----------------
__global__ void __launch_bounds__(NTHREADS, 1)
gemm_kernel(const int* __restrict__ Wq, const float* __restrict__ scales,
            const float* __restrict__ zeros, float* __restrict__ out) {
    extern __shared__ char smem[];
    uint32_t sb = smem_u32(smem);
    int tid  = threadIdx.x;
    int wid  = tid >> 5;          // 0..7
    int lane = tid & 31;
    int wm   = wid >> 1;          // 0..3  -> 32 m-rows each
    int wn   = wid & 1;           // 0..1  -> 64 n-cols each

    int n0 = blockIdx.x * TILE_N;
    int m0 = blockIdx.y * TILE_M;

    // accumulators
    float acc[2][8][4];
    float O[2][8][4];
#pragma unroll
    for (int tm = 0; tm < 2; tm++)
#pragma unroll
        for (int tn = 0; tn < 8; tn++)
#pragma unroll
            for (int c = 0; c < 4; c++) { acc[tm][tn][c] = 0.f; O[tm][tn][c] = 0.f; }

    // ldmatrix lane-row offsets (buffer-relative)
    int rowA = wm * 32 + (lane & 15);
    int sA   = rowA & 7;                 // same for rowA and rowA+16
    int hA   = lane >> 4;                // A k-chunk half select
    uint32_t offA[2] = { (uint32_t)rowA * 256u, (uint32_t)(rowA + 16) * 256u };

    int sB = lane & 7;
    int hB = (lane >> 3) & 1;
    uint32_t offB[4];
#pragma unroll
    for (int j = 0; j < 4; j++) {
        int rowB = wn * 64 + j * 16 + ((lane >> 4) << 3) + (lane & 7);
        offB[j] = (uint32_t)rowB * 256u;
    }

    // ---------------- prologue: stage group 0 ----------------
    uint32_t wv[8];
    fill_group_async(sb + 0, 0, m0, n0, scales, zeros, tid);
    CP_COMMIT();
    ldg_w(wv, Wq, 0, n0, wid, lane);
    sts_b(smem, 0, wv, wid, lane);
    CP_WAIT0();
    __syncthreads();

    for (int g = 0; g < NG_DIM; g++) {
        uint32_t curoff = (uint32_t)(g & 1) * BUF_STRIDE;
        uint32_t nxtoff = curoff ^ BUF_STRIDE;
        bool more = (g + 1 < NG_DIM);

        // stage group g+1: A/scales via cp.async, W into regs
        if (more) {
            fill_group_async(sb + nxtoff, g + 1, m0, n0, scales, zeros, tid);
            CP_COMMIT();
            ldg_w(wv, Wq, g + 1, n0, wid, lane);
        }

        // prefetch group sums for epilogue
        float Sv[4];
        {
            const float* Sg = g_S + (size_t)g * M_DIM + m0 + wm * 32 + (lane >> 2);
            Sv[0] = Sg[0]; Sv[1] = Sg[8]; Sv[2] = Sg[16]; Sv[3] = Sg[24];
        }

        uint32_t aHi = sb + curoff + B_AHI;
        uint32_t aLo = sb + curoff + B_ALO;
        uint32_t bBs = sb + curoff + B_BB;

        // ---- compute: 8 k16 steps, hi+lo planes into same accumulators ----
#pragma unroll
        for (int k16 = 0; k16 < 8; k16++) {
            uint32_t b[16];
            uint32_t cB = (uint32_t)(((2 * k16 + hB) ^ sB) << 4);
#pragma unroll
            for (int j = 0; j < 4; j++)
                LDSM_X4(b[j * 4], b[j * 4 + 1], b[j * 4 + 2], b[j * 4 + 3], bBs + offB[j] + cB);
            uint32_t cA = (uint32_t)(((2 * k16 + hA) ^ sA) << 4);
#pragma unroll
            for (int tm = 0; tm < 2; tm++) {
                uint32_t a[4];
                LDSM_X4(a[0], a[1], a[2], a[3], aHi + offA[tm] + cA);
#pragma unroll
                for (int j = 0; j < 4; j++) {
                    MMA16816(acc[tm][j * 2],     a, b[j * 4],     b[j * 4 + 1]);
                    MMA16816(acc[tm][j * 2 + 1], a, b[j * 4 + 2], b[j * 4 + 3]);
                }
                LDSM_X4(a[0], a[1], a[2], a[3], aLo + offA[tm] + cA);
#pragma unroll
                for (int j = 0; j < 4; j++) {
                    MMA16816(acc[tm][j * 2],     a, b[j * 4],     b[j * 4 + 1]);
                    MMA16816(acc[tm][j * 2 + 1], a, b[j * 4 + 2], b[j * 4 + 3]);
                }
            }
        }

        // ---- per-group epilogue: O += s * (P - z*S); reset P ----
        const char* szp = smem + curoff + B_SZ;
#pragma unroll
        for (int tn = 0; tn < 8; tn++) {
            int nl = wn * 64 + tn * 8 + (lane & 3) * 2;
            float2 s2 = *(const float2*)(szp + nl * 4);
            float2 z2 = *(const float2*)(szp + 512 + nl * 4);
#pragma unroll
            for (int tm = 0; tm < 2; tm++)
#pragma unroll
                for (int c = 0; c < 4; c++) {
                    float S = Sv[tm * 2 + (c >> 1)];
                    float s = (c & 1) ? s2.y : s2.x;
                    float z = (c & 1) ? z2.y : z2.x;
                    O[tm][tn][c] = fmaf(s, fmaf(-z, S, acc[tm][tn][c]), O[tm][tn][c]);
                    acc[tm][tn][c] = 0.f;
                }
        }

        // ---- finish staging next buffer, swap ----
        if (more) {
            sts_b(smem, nxtoff, wv, wid, lane);
            CP_WAIT0();
        }
        __syncthreads();
    }

    // ---- store output ----
#pragma unroll
    for (int tm = 0; tm < 2; tm++) {
        int r1 = m0 + wm * 32 + tm * 16 + (lane >> 2);
#pragma unroll
        for (int tn = 0; tn < 8; tn++) {
            int nc = n0 + wn * 64 + tn * 8 + (lane & 3) * 2;
            *(float2*)(out + (size_t)r1 * N_DIM + nc)       = make_float2(O[tm][tn][0], O[tm][tn][1]);
            *(float2*)(out + (size_t)(r1 + 8) * N_DIM + nc) = make_float2(O[tm][tn][2], O[tm][tn][3]);
        }
    }
}

// ---------------- launch ----------------
extern "C" void kernel_launch(void* const* d_in, const int* in_sizes, int n_in,
                              void* d_out, int out_size) {
    const float* x      = (const float*)d_in[0];
    const int*   Wq     = (const int*)d_in[1];
    const float* scales = (const float*)d_in[2];
    const float* zeros  = (const float*)d_in[3];
    float* out = (float*)d_out;

    cudaFuncSetAttribute(gemm_kernel, cudaFuncAttributeMaxDynamicSharedMemorySize, SMEM_BYTES);

    int total_threads = M_DIM * NG_DIM * 32;
    prep_kernel<<<total_threads / 256, 256>>>(x);

    dim3 grid(NT, MT);
    gemm_kernel<<<grid, NTHREADS, SMEM_BYTES>>>(Wq, scales, zeros, out);
}